// round 3
// baseline (speedup 1.0000x reference)
#include <cuda_runtime.h>
#include <cuda_bf16.h>
#include <math.h>

// ---------------------------------------------------------------------------
// MultiDEQPDEBlock: DEQ fixed-point PDE solver
//   B=8, H=W=256, hid=32 (4 GN groups), shid=16
//   core_f: conv3x3(4->32) -> GN(4) -> GELU(erf) -> conv3x3(32->1) -> damped update
// NOTE: iteration diverges at pixels with |1-mask|>1 -> values reach ~1e37.
// All overflow paths must mirror jax semantics (var->inf, rstd->0, xn->0).
// ---------------------------------------------------------------------------

#define BATCH 8
#define HH 256
#define WW 256
#define PIX (HH*WW)            // 65536
#define HID 32
#define SHID 16
#define GROUPS 4
#define CPG 8                   // channels per group
#define EPS 1e-5f
#define TOL 1e-4f
#define MAX_ITER 50
#define CFL_SCALE 0.015625f     // (32/256)^2

// ---- scratch (device globals; no cudaMalloc allowed) ----
__device__ float g_h[(size_t)BATCH*HID*PIX];      // 64 MB  conv1 output (pre-GN)
__device__ float g_sh[(size_t)BATCH*SHID*PIX];    // 32 MB  stabilizer hidden
__device__ float g_alpha[(size_t)BATCH*PIX];      // 2 MB
__device__ float g_z[(size_t)BATCH*PIX];          // 2 MB
__device__ float g_gamma[BATCH];
__device__ float g_part[BATCH*256*GROUPS*2];      // conv1 GN partials per block
__device__ float g_scale[BATCH*HID];
__device__ float g_shift[BATCH*HID];
__device__ float g_diffpart[BATCH*256];
__device__ int   g_converged;

__device__ __forceinline__ float gelu_f(float x) {
    return 0.5f * x * (1.0f + erff(x * 0.70710678118654752f));
}
__device__ __forceinline__ float sigmoid_f(float x) {
    return 1.0f / (1.0f + expf(-x));
}

// ---------------------------------------------------------------------------
// init: z = boundary, converged = 0
// ---------------------------------------------------------------------------
__global__ void init_kernel(const float* __restrict__ inp) {
    int idx = blockIdx.x * 256 + threadIdx.x;
    if (idx == 0) g_converged = 0;
    if (idx < BATCH * PIX) {
        int b = idx >> 16, pix = idx & 65535;
        g_z[idx] = inp[(size_t)b * 3 * PIX + pix];   // channel 0 = boundary
    }
}

// ---------------------------------------------------------------------------
// stabilizer conv1: 3->16, GELU
// ---------------------------------------------------------------------------
__global__ void __launch_bounds__(256) stab1_kernel(
    const float* __restrict__ inp, const float* __restrict__ w,
    const float* __restrict__ bias)
{
    const int b = blockIdx.z;
    const int tx0 = blockIdx.x * 16, ty0 = blockIdx.y * 16;
    __shared__ float s_in[3][18][18];
    __shared__ float s_w[27][16];
    __shared__ float s_b[16];
    int tid = threadIdx.y * 16 + threadIdx.x;

    for (int i = tid; i < SHID * 27; i += 256) {
        int oc = i / 27, r = i % 27;
        s_w[r][oc] = w[i];
    }
    if (tid < SHID) s_b[tid] = bias[tid];

    const float* bp = inp + (size_t)b * 3 * PIX;
    for (int i = tid; i < 3 * 324; i += 256) {
        int c = i / 324, r = i % 324, yy = r / 18, xx = r % 18;
        int gy = ty0 + yy - 1, gx = tx0 + xx - 1;
        float v = 0.f;
        if ((unsigned)gy < 256u && (unsigned)gx < 256u)
            v = bp[c * PIX + gy * WW + gx];
        s_in[c][yy][xx] = v;
    }
    __syncthreads();

    int ty = threadIdx.y, tx = threadIdx.x;
    float in[27];
#pragma unroll
    for (int c = 0; c < 3; c++)
#pragma unroll
        for (int ky = 0; ky < 3; ky++)
#pragma unroll
            for (int kx = 0; kx < 3; kx++)
                in[c * 9 + ky * 3 + kx] = s_in[c][ty + ky][tx + kx];

    float acc[SHID];
#pragma unroll
    for (int oc = 0; oc < SHID; oc++) acc[oc] = s_b[oc];
#pragma unroll
    for (int r = 0; r < 27; r++) {
        float iv = in[r];
#pragma unroll
        for (int oc = 0; oc < SHID; oc++) acc[oc] += iv * s_w[r][oc];
    }

    int pix = (ty0 + ty) * WW + (tx0 + tx);
    float* out = g_sh + (size_t)b * SHID * PIX + pix;
#pragma unroll
    for (int oc = 0; oc < SHID; oc++)
        out[oc * PIX] = gelu_f(acc[oc]);
}

// ---------------------------------------------------------------------------
// stabilizer conv2: 16->1, sigmoid -> alpha
// ---------------------------------------------------------------------------
__global__ void __launch_bounds__(256) stab2_kernel(
    const float* __restrict__ w, const float* __restrict__ bias)
{
    const int b = blockIdx.z;
    const int tx0 = blockIdx.x * 16, ty0 = blockIdx.y * 16;
    __shared__ float s_in[SHID][18][18];
    __shared__ float s_w[SHID * 9];
    int tid = threadIdx.y * 16 + threadIdx.x;

    if (tid < SHID * 9) s_w[tid] = w[tid];
    const float* hp = g_sh + (size_t)b * SHID * PIX;
    for (int i = tid; i < SHID * 324; i += 256) {
        int c = i / 324, r = i % 324, yy = r / 18, xx = r % 18;
        int gy = ty0 + yy - 1, gx = tx0 + xx - 1;
        float v = 0.f;
        if ((unsigned)gy < 256u && (unsigned)gx < 256u)
            v = hp[c * PIX + gy * WW + gx];
        s_in[c][yy][xx] = v;
    }
    __syncthreads();

    int ty = threadIdx.y, tx = threadIdx.x;
    float acc = bias[0];
#pragma unroll
    for (int c = 0; c < SHID; c++)
#pragma unroll
        for (int ky = 0; ky < 3; ky++)
#pragma unroll
            for (int kx = 0; kx < 3; kx++)
                acc += s_w[c * 9 + ky * 3 + kx] * s_in[c][ty + ky][tx + kx];

    int pix = (ty0 + ty) * WW + (tx0 + tx);
    g_alpha[(size_t)b * PIX + pix] = sigmoid_f(acc);
}

// ---------------------------------------------------------------------------
// spec_ctrl: per-batch stats -> tiny MLP -> gamma[b]
// ---------------------------------------------------------------------------
__global__ void spec_kernel(const float* __restrict__ inp,
                            const float* __restrict__ fc1_w, const float* __restrict__ fc1_b,
                            const float* __restrict__ fc2_w, const float* __restrict__ fc2_b)
{
    const int b = blockIdx.x;
    int tid = threadIdx.x;
    const float* bp = inp + (size_t)b * 3 * PIX;
    const float* kp = bp + 2 * PIX;
    float s1 = 0.f, q1 = 0.f, s2 = 0.f, q2 = 0.f;
    for (int i = tid; i < PIX; i += 256) {
        float bv = fabsf(bp[i]);
        s1 += bv; q1 += bv * bv;
        float kv = kp[i];
        s2 += kv; q2 += kv * kv;
    }
#pragma unroll
    for (int o = 16; o > 0; o >>= 1) {
        s1 += __shfl_down_sync(0xffffffffu, s1, o);
        q1 += __shfl_down_sync(0xffffffffu, q1, o);
        s2 += __shfl_down_sync(0xffffffffu, s2, o);
        q2 += __shfl_down_sync(0xffffffffu, q2, o);
    }
    __shared__ float red[8][4];
    int lane = tid & 31, warp = tid >> 5;
    if (lane == 0) { red[warp][0] = s1; red[warp][1] = q1; red[warp][2] = s2; red[warp][3] = q2; }
    __syncthreads();
    if (tid == 0) {
        float S1 = 0, Q1 = 0, S2 = 0, Q2 = 0;
#pragma unroll
        for (int w = 0; w < 8; w++) { S1 += red[w][0]; Q1 += red[w][1]; S2 += red[w][2]; Q2 += red[w][3]; }
        const float N = (float)PIX;
        float m1 = S1 / N, m2 = S2 / N;
        float v1 = (Q1 - N * m1 * m1) / (N - 1.0f);
        float v2 = (Q2 - N * m2 * m2) / (N - 1.0f);
        float feat[5] = { m1, sqrtf(fmaxf(v1, 0.f)), m2, sqrtf(fmaxf(v2, 0.f)), 1.0f };
        float out = fc2_b[0];
        for (int j = 0; j < 32; j++) {
            float t = fc1_b[j];
#pragma unroll
            for (int i = 0; i < 5; i++) t += feat[i] * fc1_w[j * 5 + i];
            out += gelu_f(t) * fc2_w[j];
        }
        g_gamma[b] = (0.5f + 1.5f * sigmoid_f(out)) * CFL_SCALE;
    }
}

// ---------------------------------------------------------------------------
// core conv1: [z,b,m,k](4) -> 32, write g_h + per-block GN partial sums
// ---------------------------------------------------------------------------
__global__ void __launch_bounds__(256) conv1_kernel(
    const float* __restrict__ inp, const float* __restrict__ w1,
    const float* __restrict__ b1, int check)
{
    if (check && g_converged) return;
    const int b = blockIdx.z;
    const int tx0 = blockIdx.x * 16, ty0 = blockIdx.y * 16;
    __shared__ float s_in[4][18][18];
    __shared__ float s_w[36][32];
    __shared__ float s_b[32];
    __shared__ float s_red[8][8];
    int tid = threadIdx.y * 16 + threadIdx.x;

    for (int i = tid; i < HID * 36; i += 256) {
        int oc = i / 36, r = i % 36;
        s_w[r][oc] = w1[i];
    }
    if (tid < HID) s_b[tid] = b1[tid];

    const float* zp = g_z + (size_t)b * PIX;
    const float* bp = inp + (size_t)b * 3 * PIX;
    for (int i = tid; i < 4 * 324; i += 256) {
        int c = i / 324, r = i % 324, yy = r / 18, xx = r % 18;
        int gy = ty0 + yy - 1, gx = tx0 + xx - 1;
        float v = 0.f;
        if ((unsigned)gy < 256u && (unsigned)gx < 256u) {
            int off = gy * WW + gx;
            v = (c == 0) ? zp[off] : bp[(c - 1) * PIX + off];
        }
        s_in[c][yy][xx] = v;
    }
    __syncthreads();

    int ty = threadIdx.y, tx = threadIdx.x;
    float in[36];
#pragma unroll
    for (int c = 0; c < 4; c++)
#pragma unroll
        for (int ky = 0; ky < 3; ky++)
#pragma unroll
            for (int kx = 0; kx < 3; kx++)
                in[c * 9 + ky * 3 + kx] = s_in[c][ty + ky][tx + kx];

    float acc[HID];
#pragma unroll
    for (int oc = 0; oc < HID; oc++) acc[oc] = s_b[oc];
#pragma unroll
    for (int r = 0; r < 36; r++) {
        float iv = in[r];
#pragma unroll
        for (int oc = 0; oc < HID; oc++) acc[oc] += iv * s_w[r][oc];
    }

    int pix = (ty0 + ty) * WW + (tx0 + tx);
    float* hp = g_h + (size_t)b * HID * PIX + pix;
    float gs[4] = {0, 0, 0, 0}, gq[4] = {0, 0, 0, 0};
#pragma unroll
    for (int oc = 0; oc < HID; oc++) {
        float v = acc[oc];
        hp[oc * PIX] = v;
        gs[oc >> 3] += v;
        gq[oc >> 3] += v * v;
    }
#pragma unroll
    for (int o = 16; o > 0; o >>= 1) {
#pragma unroll
        for (int g = 0; g < 4; g++) {
            gs[g] += __shfl_down_sync(0xffffffffu, gs[g], o);
            gq[g] += __shfl_down_sync(0xffffffffu, gq[g], o);
        }
    }
    int lane = tid & 31, warp = tid >> 5;
    if (lane == 0) {
#pragma unroll
        for (int g = 0; g < 4; g++) { s_red[warp][g] = gs[g]; s_red[warp][4 + g] = gq[g]; }
    }
    __syncthreads();
    if (tid < 8) {
        float v = 0.f;
#pragma unroll
        for (int w = 0; w < 8; w++) v += s_red[w][tid];
        int g = tid & 3, which = tid >> 2;
        int blin = blockIdx.y * 16 + blockIdx.x;
        g_part[((b * 256 + blin) * 4 + g) * 2 + which] = v;
    }
}

// ---------------------------------------------------------------------------
// GN stats combine: 32 blocks = (b,g). Overflow-safe to mirror jax:
//   E[x^2]=inf  ->  var=inf (NOT inf-inf=NaN)  ->  rstd=0, shift=gn_b
// ---------------------------------------------------------------------------
__global__ void gnstats_kernel(const float* __restrict__ gn_w,
                               const float* __restrict__ gn_b, int check)
{
    if (check && g_converged) return;
    int bg = blockIdx.x;
    int b = bg >> 2, g = bg & 3;
    int tid = threadIdx.x;
    float s = g_part[((b * 256 + tid) * 4 + g) * 2 + 0];
    float q = g_part[((b * 256 + tid) * 4 + g) * 2 + 1];
#pragma unroll
    for (int o = 16; o > 0; o >>= 1) {
        s += __shfl_down_sync(0xffffffffu, s, o);
        q += __shfl_down_sync(0xffffffffu, q, o);
    }
    __shared__ float red[8][2];
    int lane = tid & 31, warp = tid >> 5;
    if (lane == 0) { red[warp][0] = s; red[warp][1] = q; }
    __syncthreads();
    if (tid == 0) {
        float S = 0, Q = 0;
#pragma unroll
        for (int w = 0; w < 8; w++) { S += red[w][0]; Q += red[w][1]; }
        const float invN = 1.0f / (float)(CPG * PIX);
        float mean = S * invN;
        float Qn = Q * invN;
        // overflow-safe variance (jax: mean((x-mu)^2) -> +inf, never NaN)
        float var = isinf(Qn) ? Qn : fmaxf(Qn - mean * mean, 0.0f);
        float rstd = rsqrtf(var + EPS);   // var=inf -> rstd=0
#pragma unroll
        for (int c = 0; c < CPG; c++) {
            int gc = g * CPG + c;
            float sc = gn_w[gc] * rstd;
            g_scale[b * HID + gc] = sc;
            // rstd==0: ref gives xn=0 -> out = gn_b (avoid mean*0 NaN when mean=inf)
            g_shift[b * HID + gc] = (rstd == 0.0f) ? gn_b[gc] : (gn_b[gc] - mean * sc);
        }
    }
}

// ---------------------------------------------------------------------------
// fused: GN->GELU->conv2(32->1)->damped update (+diff partials in iter mode)
//   mode 0: in-place on g_z, check flag, write diff partials
//   mode 1: read g_z, write d_out (final core_f, always runs)
// ---------------------------------------------------------------------------
__global__ void __launch_bounds__(256) fused2_kernel(
    const float* __restrict__ inp, const float* __restrict__ w2,
    const float* __restrict__ b2, float* __restrict__ final_out, int mode)
{
    if (mode == 0 && g_converged) return;
    const int b = blockIdx.z;
    const int tx0 = blockIdx.x * 16, ty0 = blockIdx.y * 16;
    __shared__ float s_h[HID][18][18];
    __shared__ float s_w[HID * 9];
    __shared__ float s_sc[HID], s_sf[HID];
    __shared__ float s_red[8];
    int tid = threadIdx.y * 16 + threadIdx.x;

    // HID*9 = 288 > 256: strided loop required
    for (int i = tid; i < HID * 9; i += 256) s_w[i] = w2[i];
    if (tid < HID) { s_sc[tid] = g_scale[b * HID + tid]; s_sf[tid] = g_shift[b * HID + tid]; }
    __syncthreads();

    const float* hp = g_h + (size_t)b * HID * PIX;
    for (int i = tid; i < HID * 324; i += 256) {
        int c = i / 324, r = i % 324, yy = r / 18, xx = r % 18;
        int gy = ty0 + yy - 1, gx = tx0 + xx - 1;
        float v = 0.f;
        if ((unsigned)gy < 256u && (unsigned)gx < 256u) {
            float hv = hp[c * PIX + gy * WW + gx];
            float sc = s_sc[c];
            // sc==0 <=> overflow regime; hv may be +/-inf; ref gives xn=0 -> gn_b.
            // Skip hv*sc product to avoid inf*0=NaN.
            v = (sc == 0.0f) ? s_sf[c] : (hv * sc + s_sf[c]);
            v = gelu_f(v);
        }
        s_h[c][yy][xx] = v;
    }
    __syncthreads();

    int ty = threadIdx.y, tx = threadIdx.x;
    float acc = b2[0];
#pragma unroll
    for (int c = 0; c < HID; c++)
#pragma unroll
        for (int ky = 0; ky < 3; ky++)
#pragma unroll
            for (int kx = 0; kx < 3; kx++)
                acc += s_w[c * 9 + ky * 3 + kx] * s_h[c][ty + ky][tx + kx];

    int pix = (ty0 + ty) * WW + (tx0 + tx);
    int off = b * PIX + pix;
    const float* bp = inp + (size_t)b * 3 * PIX;
    float zold = g_z[off];
    // mirror XLA elementwise rounding exactly (no FMA contraction):
    // z_new = z + (gamma*alpha)*dz ; res = z_new*(1-m) + boundary*m
    float ga   = __fmul_rn(g_gamma[b], g_alpha[off]);
    float znew = __fadd_rn(zold, __fmul_rn(ga, acc));
    float m  = bp[PIX + pix];
    float bv = bp[pix];
    float res = __fadd_rn(__fmul_rn(znew, __fadd_rn(1.0f, -m)), __fmul_rn(bv, m));
    if (mode == 0) {
        g_z[off] = res;
        float d = __fadd_rn(res, -zold);
        float s = d * d;
#pragma unroll
        for (int o = 16; o > 0; o >>= 1) s += __shfl_down_sync(0xffffffffu, s, o);
        int lane = tid & 31, warp = tid >> 5;
        if (lane == 0) s_red[warp] = s;
        __syncthreads();
        if (tid == 0) {
            float t = 0.f;
#pragma unroll
            for (int w = 0; w < 8; w++) t += s_red[w];
            int blin = blockIdx.y * 16 + blockIdx.x;
            g_diffpart[b * 256 + blin] = t;
        }
    } else {
        final_out[off] = res;
    }
}

// ---------------------------------------------------------------------------
// diff combine: mean over batch of per-batch L2 norms; set flag.
// jax cond: continue while (diff >= TOL); NaN diff -> STOP. Use !(m>=TOL).
// ---------------------------------------------------------------------------
__global__ void diff_kernel()
{
    if (g_converged) return;
    int tid = threadIdx.x;
    int w = tid >> 5, lane = tid & 31;   // warp w handles batch w
    float s = 0.f;
    for (int i = lane; i < 256; i += 32) s += g_diffpart[w * 256 + i];
#pragma unroll
    for (int o = 16; o > 0; o >>= 1) s += __shfl_down_sync(0xffffffffu, s, o);
    __shared__ float sb[8];
    if (lane == 0) sb[w] = sqrtf(s);
    __syncthreads();
    if (tid == 0) {
        float m = 0.f;
#pragma unroll
        for (int bb = 0; bb < 8; bb++) m += sb[bb];
        m *= 0.125f;
        if (!(m >= TOL)) g_converged = 1;   // matches jax: NaN also stops
    }
}

// ---------------------------------------------------------------------------
extern "C" void kernel_launch(void* const* d_in, const int* in_sizes, int n_in,
                              void* d_out, int out_size)
{
    const float* inp     = (const float*)d_in[0];
    const float* core_w1 = (const float*)d_in[1];
    const float* core_b1 = (const float*)d_in[2];
    const float* gn_w    = (const float*)d_in[3];
    const float* gn_b    = (const float*)d_in[4];
    const float* core_w2 = (const float*)d_in[5];
    const float* core_b2 = (const float*)d_in[6];
    const float* stab_w1 = (const float*)d_in[7];
    const float* stab_b1 = (const float*)d_in[8];
    const float* stab_w2 = (const float*)d_in[9];
    const float* stab_b2 = (const float*)d_in[10];
    const float* fc1_w   = (const float*)d_in[11];
    const float* fc1_b   = (const float*)d_in[12];
    const float* fc2_w   = (const float*)d_in[13];
    const float* fc2_b   = (const float*)d_in[14];
    float* out = (float*)d_out;

    dim3 blk(16, 16);
    dim3 grd(16, 16, BATCH);

    init_kernel<<<2048, 256>>>(inp);
    stab1_kernel<<<grd, blk>>>(inp, stab_w1, stab_b1);
    stab2_kernel<<<grd, blk>>>(stab_w2, stab_b2);
    spec_kernel<<<BATCH, 256>>>(inp, fc1_w, fc1_b, fc2_w, fc2_b);

    for (int it = 0; it < MAX_ITER; ++it) {
        conv1_kernel<<<grd, blk>>>(inp, core_w1, core_b1, 1);
        gnstats_kernel<<<32, 256>>>(gn_w, gn_b, 1);
        fused2_kernel<<<grd, blk>>>(inp, core_w2, core_b2, nullptr, 0);
        diff_kernel<<<1, 256>>>();
    }
    // final core_f (always runs): z_star -> d_out
    conv1_kernel<<<grd, blk>>>(inp, core_w1, core_b1, 0);
    gnstats_kernel<<<32, 256>>>(gn_w, gn_b, 0);
    fused2_kernel<<<grd, blk>>>(inp, core_w2, core_b2, out, 1);
}